// round 1
// baseline (speedup 1.0000x reference)
#include <cuda_runtime.h>
#include <stdint.h>

// ============================================================================
// JMEFairnessLoss — full pipeline:
//   K1  : partial sums of true_scores           (mean -> target exposure)
//   K1b : finalize mean -> g_t
//   K2  : per-row stable top-100 (radix select + bitonic tie-break sort)
//   K3  : threefry gumbel noise + soft-rank exposure + per-row partials
//   K4  : final deterministic reductions -> (total, ii, gg)
// No device allocation, no cross-block atomics -> deterministic & capturable.
// ============================================================================

// JAX >= 0.4.30 defaults jax_threefry_partitionable=True.
// If rel_err comes back O(1e-2..1), flip this to 0 (legacy split-iota mode).
#define THREEFRY_PARTITIONABLE 1

namespace jme {
constexpr int B      = 1024;
constexpr int NITEMS = 10000;
constexpr int TOPK   = 100;
constexpr int NS     = 10;
constexpr int NIG    = 16;
constexpr int NPAIR  = 128;   // 8 user groups * 16 item groups
constexpr int NTOT   = NS * B * TOPK;   // 1,024,000 noise elements
constexpr int NHALF  = NTOT / 2;
}

// ------------------------------- scratch (device globals, no allocs) -------
__device__ float g_tpart[256];
__device__ float g_t;
__device__ float g_topk_val[jme::B * jme::TOPK];
__device__ int   g_topk_grp[jme::B * jme::TOPK];
__device__ float g_row_ii[jme::B];
__device__ float g_grpD[jme::B * jme::NIG];
__device__ float g_grpC[jme::B * jme::NIG];

// ------------------------------- threefry2x32 (JAX-exact) ------------------
__device__ __forceinline__ void tf_round(uint32_t& x0, uint32_t& x1, int r) {
    x0 += x1;
    x1 = __funnelshift_l(x1, x1, r);   // rotl32
    x1 ^= x0;
}

// key = (0, 1)  <- jax.random.key(1)
__device__ __forceinline__ uint2 threefry01(uint32_t x0, uint32_t x1) {
    const uint32_t k0 = 0u, k1 = 1u, k2 = 0x1BD11BDBu;  // 0x1BD11BDA ^ 0 ^ 1
    x0 += k0; x1 += k1;
    tf_round(x0,x1,13); tf_round(x0,x1,15); tf_round(x0,x1,26); tf_round(x0,x1,6);
    x0 += k1; x1 += k2 + 1u;
    tf_round(x0,x1,17); tf_round(x0,x1,29); tf_round(x0,x1,16); tf_round(x0,x1,24);
    x0 += k2; x1 += k0 + 2u;
    tf_round(x0,x1,13); tf_round(x0,x1,15); tf_round(x0,x1,26); tf_round(x0,x1,6);
    x0 += k0; x1 += k1 + 3u;
    tf_round(x0,x1,17); tf_round(x0,x1,29); tf_round(x0,x1,16); tf_round(x0,x1,24);
    x0 += k1; x1 += k2 + 4u;
    tf_round(x0,x1,13); tf_round(x0,x1,15); tf_round(x0,x1,26); tf_round(x0,x1,6);
    x0 += k2; x1 += k0 + 5u;
    return make_uint2(x0, x1);
}

// gumbel(key(1)) element at linear index `lin` in the (S,B,K) tensor
__device__ __forceinline__ float gumbel_at(int lin) {
    uint32_t bits;
#if THREEFRY_PARTITIONABLE
    // counter = uint64 linear index: hi = 0, lo = lin; 32-bit draw = out0 ^ out1
    uint2 r = threefry01(0u, (uint32_t)lin);
    bits = r.x ^ r.y;
#else
    // legacy: iota split in halves: x0 = i, x1 = i + N/2; concat(out0, out1)
    if (lin < jme::NHALF) {
        uint2 r = threefry01((uint32_t)lin, (uint32_t)(lin + jme::NHALF));
        bits = r.x;
    } else {
        uint2 r = threefry01((uint32_t)(lin - jme::NHALF), (uint32_t)lin);
        bits = r.y;
    }
#endif
    // jax uniform(minval=tiny, maxval=1): mantissa-fill trick then clamp
    float f = __uint_as_float((bits >> 9) | 0x3F800000u) - 1.0f;   // [0,1)
    float u = fmaxf(1.17549435e-38f, f);
    return -logf(-logf(u));
}

// ------------------------------- K1: mean(true_scores) ---------------------
__global__ __launch_bounds__(256) void k_mean_part(const float* __restrict__ ts) {
    float s = 0.0f;
    const int n = jme::B * jme::NITEMS;
    for (int i = blockIdx.x * blockDim.x + threadIdx.x; i < n; i += gridDim.x * blockDim.x)
        s += ts[i];
    __shared__ float red[256];
    red[threadIdx.x] = s; __syncthreads();
    for (int o = 128; o > 0; o >>= 1) {
        if (threadIdx.x < o) red[threadIdx.x] += red[threadIdx.x + o];
        __syncthreads();
    }
    if (threadIdx.x == 0) g_tpart[blockIdx.x] = red[0];
}

__global__ __launch_bounds__(256) void k_mean_final() {
    __shared__ float red[256];
    red[threadIdx.x] = g_tpart[threadIdx.x]; __syncthreads();
    for (int o = 128; o > 0; o >>= 1) {
        if (threadIdx.x < o) red[threadIdx.x] += red[threadIdx.x + o];
        __syncthreads();
    }
    if (threadIdx.x == 0) g_t = red[0] / (float)(jme::B * jme::NITEMS);
}

// ------------------------------- K2: stable top-100 per row ----------------
// Key transform: monotonic float->uint32 (larger float -> larger key).
__device__ __forceinline__ uint32_t f2key(float f) {
    uint32_t u = __float_as_uint(f);
    return (u & 0x80000000u) ? ~u : (u | 0x80000000u);
}
__device__ __forceinline__ float key2f(uint32_t k) {
    uint32_t fb = (k & 0x80000000u) ? (k ^ 0x80000000u) : ~k;
    return __uint_as_float(fb);
}

__global__ __launch_bounds__(256) void k_topk(const float* __restrict__ pred,
                                              const int*   __restrict__ item_groups) {
    __shared__ uint32_t skey[jme::NITEMS];                    // 40000 B
    __shared__ unsigned long long cand[1024];                 // 8192 B (hist aliased)
    __shared__ uint32_t s_prefix;
    __shared__ int      s_rem;
    __shared__ int      s_cnt;
    uint32_t* hist = (uint32_t*)cand;                         // first 1 KB reused

    const int row = blockIdx.x, tid = threadIdx.x, bd = blockDim.x;
    const float* rp = pred + (size_t)row * jme::NITEMS;

    for (int i = tid; i < jme::NITEMS; i += bd) skey[i] = f2key(rp[i]);
    if (tid == 0) { s_rem = jme::TOPK; s_prefix = 0u; s_cnt = 0; }
    __syncthreads();

    uint32_t prefix = 0u;
    // 4-pass radix select (descending) for the 100th largest key
    for (int shift = 24; shift >= 0; shift -= 8) {
        for (int i = tid; i < 256; i += bd) hist[i] = 0u;
        __syncthreads();
        const uint32_t himask = (shift == 24) ? 0u : (0xFFFFFFFFu << (shift + 8));
        for (int i = tid; i < jme::NITEMS; i += bd) {
            uint32_t k = skey[i];
            if ((k & himask) == prefix) {
                int bin = (k >> shift) & 0xFF;
                unsigned m = __match_any_sync(__activemask(), bin);
                if ((tid & 31) == (__ffs(m) - 1)) atomicAdd(&hist[bin], __popc(m));
            }
        }
        __syncthreads();
        if (tid == 0) {
            int cum = 0, sel = 0;
            for (int b = 255; b >= 0; --b) {
                int h = (int)hist[b];
                if (cum + h >= s_rem) { sel = b; s_rem -= cum; break; }
                cum += h;
            }
            s_prefix = prefix | ((uint32_t)sel << shift);
        }
        __syncthreads();
        prefix = s_prefix;
        __syncthreads();
    }
    const uint32_t T = prefix;   // threshold key (100th largest)

    // gather all keys >= T; entry = (~key << 32) | idx, so ASCENDING u64 sort
    // gives (value desc, index asc) — jax.lax.top_k stable semantics exactly.
    for (int i = tid; i < 1024; i += bd) cand[i] = 0xFFFFFFFFFFFFFFFFULL;
    __syncthreads();
    for (int i = tid; i < jme::NITEMS; i += bd) {
        uint32_t k = skey[i];
        if (k >= T) {
            int pos = atomicAdd(&s_cnt, 1);
            if (pos < 1024)
                cand[pos] = (((unsigned long long)(~k)) << 32) | (uint32_t)i;
        }
    }
    __syncthreads();

    // bitonic sort 1024 u64 ascending
    for (int kk = 2; kk <= 1024; kk <<= 1) {
        for (int j = kk >> 1; j > 0; j >>= 1) {
            for (int i = tid; i < 1024; i += bd) {
                int ixj = i ^ j;
                if (ixj > i) {
                    unsigned long long a = cand[i], b = cand[ixj];
                    bool asc = ((i & kk) == 0);
                    if (asc ? (a > b) : (a < b)) { cand[i] = b; cand[ixj] = a; }
                }
            }
            __syncthreads();
        }
    }

    if (tid < jme::TOPK) {
        unsigned long long e = cand[tid];
        uint32_t idx = (uint32_t)e;
        uint32_t key = ~(uint32_t)(e >> 32);
        g_topk_val[row * jme::TOPK + tid] = key2f(key);
        g_topk_grp[row * jme::TOPK + tid] = item_groups[idx];
    }
}

// ------------------------------- K3: exposure + per-row partials -----------
__global__ __launch_bounds__(128) void k_exposure() {
    const int b = blockIdx.x, tid = threadIdx.x;
    __shared__ float noisy[jme::TOPK];
    __shared__ float sdelta[jme::TOPK];
    __shared__ int   s_ig[jme::TOPK];

    const float t = g_t;
    float sc = 0.0f; int ig = 0;
    if (tid < jme::TOPK) {
        sc = g_topk_val[b * jme::TOPK + tid];
        ig = g_topk_grp[b * jme::TOPK + tid];
    }

    const float LOG2_GAMMA = -0.321928094887f;   // log2(0.8)
    float expo = 0.0f;

    for (int s = 0; s < jme::NS; ++s) {
        if (tid < jme::TOPK) {
            int lin = (s * jme::B + b) * jme::TOPK + tid;
            noisy[tid] = sc + gumbel_at(lin);
        }
        __syncthreads();
        if (tid < jme::TOPK) {
            const float ni = noisy[tid];
            float r = 0.0f;
            #pragma unroll 4
            for (int j = 0; j < jme::TOPK; ++j) {
                float x = (ni - noisy[j]) * 10.0f;            // diff / TAU
                // stable sigmoid: 1/(1+e^{-x}); e^{-x}=inf -> rcp -> 0 (ok)
                r += __fdividef(1.0f, 1.0f + __expf(-x));
            }
            float rank = 0.5f + r;                            // 1 + sum - 0.5
            expo += exp2f((rank - 1.0f) * LOG2_GAMMA);        // gamma^(rank-1)
        }
        __syncthreads();
    }

    if (tid < jme::TOPK) {
        sdelta[tid] = expo * 0.1f - t;   // mean over 10 samples, minus target
        s_ig[tid]   = ig;
    }
    __syncthreads();

    if (tid == 0) {                       // deterministic serial row sums
        float ii = 0.0f;
        for (int i = 0; i < jme::TOPK; ++i) ii += sdelta[i] * sdelta[i];
        g_row_ii[b] = ii;
    }
    if (tid < jme::NIG) {
        float sD = 0.0f, c = 0.0f;
        for (int i = 0; i < jme::TOPK; ++i)
            if (s_ig[i] == tid) { sD += sdelta[i]; c += 1.0f; }
        g_grpD[b * jme::NIG + tid] = sD;
        g_grpC[b * jme::NIG + tid] = c;
    }
}

// ------------------------------- K4: final losses --------------------------
__global__ __launch_bounds__(256) void k_final(const int* __restrict__ user_groups,
                                               float* __restrict__ out) {
    __shared__ float red[256];
    const int tid = threadIdx.x;

    float s = 0.0f;
    for (int r = tid; r < jme::B; r += 256) s += g_row_ii[r];
    red[tid] = s; __syncthreads();
    for (int o = 128; o > 0; o >>= 1) {
        if (tid < o) red[tid] += red[tid + o];
        __syncthreads();
    }
    const float ii = red[0] / (float)(jme::B * jme::TOPK);
    __syncthreads();

    float a2 = 0.0f;
    if (tid < jme::NPAIR) {
        const int ug = tid / jme::NIG, ig = tid % jme::NIG;
        float sD = 0.0f, c = 0.0f;
        for (int r = 0; r < jme::B; ++r) {
            if (user_groups[r] == ug) {
                sD += g_grpD[r * jme::NIG + ig];
                c  += g_grpC[r * jme::NIG + ig];
            }
        }
        float avg = (c > 0.0f) ? (sD / fmaxf(c, 1.0f)) : 0.0f;
        a2 = avg * avg;
    }
    red[tid] = a2; __syncthreads();
    for (int o = 128; o > 0; o >>= 1) {
        if (tid < o) red[tid] += red[tid + o];
        __syncthreads();
    }
    const float gg = red[0] / (float)jme::NPAIR;

    if (tid == 0) {
        out[0] = ii + gg;   // total (ALPHA = 1)
        out[1] = ii;
        out[2] = gg;
    }
}

// ------------------------------- launch -------------------------------------
extern "C" void kernel_launch(void* const* d_in, const int* in_sizes, int n_in,
                              void* d_out, int out_size) {
    const float* pred  = (const float*)d_in[0];
    const float* truth = (const float*)d_in[1];
    const int*   ug    = (const int*)  d_in[2];
    const int*   ig    = (const int*)  d_in[3];
    float* out = (float*)d_out;

    k_mean_part <<<256, 256>>>(truth);
    k_mean_final<<<1,   256>>>();
    k_topk      <<<jme::B, 256>>>(pred, ig);
    k_exposure  <<<jme::B, 128>>>();
    k_final     <<<1,   256>>>(ug, out);
}

// round 2
// speedup vs baseline: 1.8506x; 1.8506x over previous
#include <cuda_runtime.h>
#include <stdint.h>

// ============================================================================
// JMEFairnessLoss:
//   K1  : partial sums of true_scores  (mean -> target exposure)
//   K1b : finalize mean -> g_t
//   K2  : per-row stable top-100 (13-bit histogram select + 256-wide bitonic)
//   K3  : threefry gumbel + soft-rank exposure, 1000 flat tasks/row
//   K4  : final deterministic reductions -> (total, ii, gg)
// ============================================================================

namespace jme {
constexpr int B      = 1024;
constexpr int NITEMS = 10000;
constexpr int TOPK   = 100;
constexpr int NS     = 10;
constexpr int NIG    = 16;
constexpr int NPAIR  = 128;
constexpr int NTASK  = NS * TOPK;     // 1000 per row
constexpr int NBIN   = 8192;          // 13-bit histogram
constexpr int CAND   = 256;
}

// ------------------------------- scratch -----------------------------------
__device__ float g_tpart[256];
__device__ float g_t;
__device__ float g_topk_val[jme::B * jme::TOPK];
__device__ int   g_topk_grp[jme::B * jme::TOPK];
__device__ float g_row_ii[jme::B];
__device__ float g_grpD[jme::B * jme::NIG];
__device__ float g_grpC[jme::B * jme::NIG];

// ------------------------------- threefry2x32 (JAX-exact, key=(0,1)) -------
__device__ __forceinline__ void tf_round(uint32_t& x0, uint32_t& x1, int r) {
    x0 += x1;
    x1 = __funnelshift_l(x1, x1, r);
    x1 ^= x0;
}
__device__ __forceinline__ uint2 threefry01(uint32_t x0, uint32_t x1) {
    const uint32_t k0 = 0u, k1 = 1u, k2 = 0x1BD11BDBu;
    x0 += k0; x1 += k1;
    tf_round(x0,x1,13); tf_round(x0,x1,15); tf_round(x0,x1,26); tf_round(x0,x1,6);
    x0 += k1; x1 += k2 + 1u;
    tf_round(x0,x1,17); tf_round(x0,x1,29); tf_round(x0,x1,16); tf_round(x0,x1,24);
    x0 += k2; x1 += k0 + 2u;
    tf_round(x0,x1,13); tf_round(x0,x1,15); tf_round(x0,x1,26); tf_round(x0,x1,6);
    x0 += k0; x1 += k1 + 3u;
    tf_round(x0,x1,17); tf_round(x0,x1,29); tf_round(x0,x1,16); tf_round(x0,x1,24);
    x0 += k1; x1 += k2 + 4u;
    tf_round(x0,x1,13); tf_round(x0,x1,15); tf_round(x0,x1,26); tf_round(x0,x1,6);
    x0 += k2; x1 += k0 + 5u;
    return make_uint2(x0, x1);
}
__device__ __forceinline__ float gumbel_at(int lin) {
    uint2 r = threefry01(0u, (uint32_t)lin);    // partitionable mode
    uint32_t bits = r.x ^ r.y;
    float f = __uint_as_float((bits >> 9) | 0x3F800000u) - 1.0f;
    float u = fmaxf(1.17549435e-38f, f);
    return -logf(-logf(u));
}

// ------------------------------- K1 ----------------------------------------
__global__ __launch_bounds__(256) void k_mean_part(const float4* __restrict__ ts) {
    float s = 0.0f;
    const int n4 = (jme::B * jme::NITEMS) / 4;
    for (int i = blockIdx.x * blockDim.x + threadIdx.x; i < n4; i += gridDim.x * blockDim.x) {
        float4 v = ts[i];
        s += (v.x + v.y) + (v.z + v.w);
    }
    __shared__ float red[256];
    red[threadIdx.x] = s; __syncthreads();
    for (int o = 128; o > 0; o >>= 1) {
        if (threadIdx.x < o) red[threadIdx.x] += red[threadIdx.x + o];
        __syncthreads();
    }
    if (threadIdx.x == 0) g_tpart[blockIdx.x] = red[0];
}
__global__ __launch_bounds__(256) void k_mean_final() {
    __shared__ float red[256];
    red[threadIdx.x] = g_tpart[threadIdx.x]; __syncthreads();
    for (int o = 128; o > 0; o >>= 1) {
        if (threadIdx.x < o) red[threadIdx.x] += red[threadIdx.x + o];
        __syncthreads();
    }
    if (threadIdx.x == 0) g_t = red[0] / (float)(jme::B * jme::NITEMS);
}

// ------------------------------- K2: stable top-100 ------------------------
__device__ __forceinline__ uint32_t f2key(float f) {
    uint32_t u = __float_as_uint(f);
    return (u & 0x80000000u) ? ~u : (u | 0x80000000u);
}
__device__ __forceinline__ float key2f(uint32_t k) {
    uint32_t fb = (k & 0x80000000u) ? (k ^ 0x80000000u) : ~k;
    return __uint_as_float(fb);
}

__global__ __launch_bounds__(256) void k_topk(const float* __restrict__ pred,
                                              const int*   __restrict__ item_groups) {
    __shared__ uint32_t hist[jme::NBIN];                 // 32 KB
    __shared__ unsigned long long cand[jme::CAND];       // 2 KB
    __shared__ uint32_t spartial[256];
    __shared__ int s_selbin;
    __shared__ int s_cnt;

    const int row = blockIdx.x, tid = threadIdx.x;
    const float4* rp4 = (const float4*)(pred + (size_t)row * jme::NITEMS);
    constexpr int N4 = jme::NITEMS / 4;                  // 2500

    for (int i = tid; i < jme::NBIN; i += 256) hist[i] = 0u;
    if (tid == 0) s_cnt = 0;
    __syncthreads();

    // pass 1: 13-bit histogram of sort keys
    for (int c = tid; c < N4; c += 256) {
        float4 v = rp4[c];
        atomicAdd(&hist[f2key(v.x) >> 19], 1u);
        atomicAdd(&hist[f2key(v.y) >> 19], 1u);
        atomicAdd(&hist[f2key(v.z) >> 19], 1u);
        atomicAdd(&hist[f2key(v.w) >> 19], 1u);
    }
    __syncthreads();

    // suffix scan: find highest bin where cumulative (from top) reaches TOPK
    {
        uint32_t p = 0;
        const int base = tid * 32;
        #pragma unroll
        for (int b = 0; b < 32; ++b) p += hist[base + b];
        spartial[tid] = p;
    }
    __syncthreads();
    if (tid == 0) {
        int cum = 0, sel = 0;
        for (int t = 255; t >= 0; --t) {
            int p = (int)spartial[t];
            if (cum + p >= jme::TOPK) {
                for (int b = t * 32 + 31; b >= t * 32; --b) {
                    cum += (int)hist[b];
                    if (cum >= jme::TOPK) { sel = b; break; }
                }
                break;
            }
            cum += p;
        }
        s_selbin = sel;
    }
    __syncthreads();
    const uint32_t selbin = (uint32_t)s_selbin;

    for (int i = tid; i < jme::CAND; i += 256) cand[i] = 0xFFFFFFFFFFFFFFFFULL;
    __syncthreads();

    // pass 2: gather candidates (bin >= selbin); expected count ~100-160
    for (int c = tid; c < N4; c += 256) {
        float4 v = rp4[c];
        const float vv[4] = {v.x, v.y, v.z, v.w};
        #pragma unroll
        for (int e = 0; e < 4; ++e) {
            uint32_t k = f2key(vv[e]);
            if ((k >> 19) >= selbin) {
                int pos = atomicAdd(&s_cnt, 1);
                if (pos < jme::CAND)
                    cand[pos] = (((unsigned long long)(~k)) << 32) | (uint32_t)(4 * c + e);
            }
        }
    }
    __syncthreads();

    // bitonic sort 256 u64 ascending: (~key, idx) asc == (value desc, idx asc)
    #pragma unroll
    for (int kk = 2; kk <= jme::CAND; kk <<= 1) {
        for (int j = kk >> 1; j > 0; j >>= 1) {
            int i = tid, ixj = i ^ j;
            if (ixj > i) {
                unsigned long long a = cand[i], b = cand[ixj];
                bool asc = ((i & kk) == 0);
                if (asc ? (a > b) : (a < b)) { cand[i] = b; cand[ixj] = a; }
            }
            __syncthreads();
        }
    }

    if (tid < jme::TOPK) {
        unsigned long long e = cand[tid];
        uint32_t idx = (uint32_t)e;
        uint32_t key = ~(uint32_t)(e >> 32);
        g_topk_val[row * jme::TOPK + tid] = key2f(key);
        g_topk_grp[row * jme::TOPK + tid] = item_groups[idx];
    }
}

// ------------------------------- K3: exposure ------------------------------
__global__ __launch_bounds__(128) void k_exposure() {
    const int b = blockIdx.x, tid = threadIdx.x;
    __shared__ float sval[jme::TOPK];
    __shared__ float nz[jme::NS][jme::TOPK];   // noisy * (10*log2(e))
    __shared__ float expo_sb[jme::NTASK];      // per (s,i) exposure
    __shared__ float sdelta[jme::TOPK];
    __shared__ int   s_ig[jme::TOPK];

    const float t = g_t;
    if (tid < jme::TOPK) {
        sval[tid] = g_topk_val[b * jme::TOPK + tid];
        s_ig[tid] = g_topk_grp[b * jme::TOPK + tid];
    }
    __syncthreads();

    const float SCL = 14.4269504089f;          // 10 / tau-normalized * log2(e)
    // generate pre-scaled noisy scores: 1000 tasks over 128 threads
    for (int tk = tid; tk < jme::NTASK; tk += 128) {
        int s = tk / jme::TOPK, i = tk - s * jme::TOPK;
        int lin = (s * jme::B + b) * jme::TOPK + i;
        nz[s][i] = (sval[i] + gumbel_at(lin)) * SCL;
    }
    __syncthreads();

    const float LOG2_GAMMA = -0.3219280948873623f;  // log2(0.8)
    for (int tk = tid; tk < jme::NTASK; tk += 128) {
        int s = tk / jme::TOPK, i = tk - s * jme::TOPK;
        const float* rowp = nz[s];
        const float vi = rowp[i];
        float r0 = 0.0f, r1 = 0.0f;
        #pragma unroll 4
        for (int j = 0; j < jme::TOPK; j += 2) {
            float d0 = rowp[j]     - vi;   // sigmoid((vi-vj)*10) = 1/(1+2^d)
            float d1 = rowp[j + 1] - vi;
            float e0, e1, q0, q1;
            asm("ex2.approx.f32 %0, %1;" : "=f"(e0) : "f"(d0));
            asm("ex2.approx.f32 %0, %1;" : "=f"(e1) : "f"(d1));
            asm("rcp.approx.f32 %0, %1;" : "=f"(q0) : "f"(1.0f + e0));
            asm("rcp.approx.f32 %0, %1;" : "=f"(q1) : "f"(1.0f + e1));
            r0 += q0; r1 += q1;
        }
        float rank_m1 = (r0 + r1) - 0.5f;          // ranks - 1
        float ex;
        asm("ex2.approx.f32 %0, %1;" : "=f"(ex) : "f"(rank_m1 * LOG2_GAMMA));
        expo_sb[tk] = ex;
    }
    __syncthreads();

    if (tid < jme::TOPK) {
        float acc = 0.0f;
        #pragma unroll
        for (int s = 0; s < jme::NS; ++s) acc += expo_sb[s * jme::TOPK + tid];
        sdelta[tid] = acc * 0.1f - t;
    }
    __syncthreads();

    if (tid == 0) {
        float ii = 0.0f;
        for (int i = 0; i < jme::TOPK; ++i) ii += sdelta[i] * sdelta[i];
        g_row_ii[b] = ii;
    }
    if (tid < jme::NIG) {
        float sD = 0.0f, c = 0.0f;
        for (int i = 0; i < jme::TOPK; ++i)
            if (s_ig[i] == tid) { sD += sdelta[i]; c += 1.0f; }
        g_grpD[b * jme::NIG + tid] = sD;
        g_grpC[b * jme::NIG + tid] = c;
    }
}

// ------------------------------- K4 ----------------------------------------
__global__ __launch_bounds__(256) void k_final(const int* __restrict__ user_groups,
                                               float* __restrict__ out) {
    __shared__ float red[256];
    const int tid = threadIdx.x;

    float s = 0.0f;
    for (int r = tid; r < jme::B; r += 256) s += g_row_ii[r];
    red[tid] = s; __syncthreads();
    for (int o = 128; o > 0; o >>= 1) {
        if (tid < o) red[tid] += red[tid + o];
        __syncthreads();
    }
    const float ii = red[0] / (float)(jme::B * jme::TOPK);
    __syncthreads();

    float a2 = 0.0f;
    if (tid < jme::NPAIR) {
        const int ug = tid / jme::NIG, ig = tid % jme::NIG;
        float sD = 0.0f, c = 0.0f;
        for (int r = 0; r < jme::B; ++r) {
            if (user_groups[r] == ug) {
                sD += g_grpD[r * jme::NIG + ig];
                c  += g_grpC[r * jme::NIG + ig];
            }
        }
        float avg = (c > 0.0f) ? (sD / fmaxf(c, 1.0f)) : 0.0f;
        a2 = avg * avg;
    }
    red[tid] = a2; __syncthreads();
    for (int o = 128; o > 0; o >>= 1) {
        if (tid < o) red[tid] += red[tid + o];
        __syncthreads();
    }
    const float gg = red[0] / (float)jme::NPAIR;

    if (tid == 0) {
        out[0] = ii + gg;
        out[1] = ii;
        out[2] = gg;
    }
}

// ------------------------------- launch ------------------------------------
extern "C" void kernel_launch(void* const* d_in, const int* in_sizes, int n_in,
                              void* d_out, int out_size) {
    const float* pred  = (const float*)d_in[0];
    const float* truth = (const float*)d_in[1];
    const int*   ug    = (const int*)  d_in[2];
    const int*   ig    = (const int*)  d_in[3];
    float* out = (float*)d_out;

    k_mean_part <<<256, 256>>>((const float4*)truth);
    k_mean_final<<<1,   256>>>();
    k_topk      <<<jme::B, 256>>>(pred, ig);
    k_exposure  <<<jme::B, 128>>>();
    k_final     <<<1,   256>>>(ug, out);
}

// round 3
// speedup vs baseline: 2.5627x; 1.3848x over previous
#include <cuda_runtime.h>
#include <stdint.h>

// ============================================================================
// JMEFairnessLoss:
//   K1  : partial sums of true_scores  (mean -> target exposure)
//   K1b : finalize mean -> g_t
//   K2  : per-row stable top-100: threshold gather (T=2.10, 5.9-sigma margins)
//         + 256-wide bitonic; exact radix-select fallback for any bad row
//   K3  : threefry gumbel + soft-rank via tanh.approx (1 MUFU/sigmoid)
//   K4  : final deterministic reductions -> (total, ii, gg)
// ============================================================================

namespace jme {
constexpr int B      = 1024;
constexpr int NITEMS = 10000;
constexpr int TOPK   = 100;
constexpr int NS     = 10;
constexpr int NIG    = 16;
constexpr int NPAIR  = 128;
constexpr int NTASK  = NS * TOPK;     // 1000 per row
constexpr int CAND   = 256;
}

// ------------------------------- scratch -----------------------------------
__device__ float g_tpart[256];
__device__ float g_t;
__device__ float g_topk_val[jme::B * jme::TOPK];
__device__ int   g_topk_grp[jme::B * jme::TOPK];
__device__ float g_row_ii[jme::B];
__device__ float g_grpD[jme::B * jme::NIG];
__device__ float g_grpC[jme::B * jme::NIG];

// ------------------------------- threefry2x32 (JAX-exact, key=(0,1)) -------
__device__ __forceinline__ void tf_round(uint32_t& x0, uint32_t& x1, int r) {
    x0 += x1;
    x1 = __funnelshift_l(x1, x1, r);
    x1 ^= x0;
}
__device__ __forceinline__ uint2 threefry01(uint32_t x0, uint32_t x1) {
    const uint32_t k0 = 0u, k1 = 1u, k2 = 0x1BD11BDBu;
    x0 += k0; x1 += k1;
    tf_round(x0,x1,13); tf_round(x0,x1,15); tf_round(x0,x1,26); tf_round(x0,x1,6);
    x0 += k1; x1 += k2 + 1u;
    tf_round(x0,x1,17); tf_round(x0,x1,29); tf_round(x0,x1,16); tf_round(x0,x1,24);
    x0 += k2; x1 += k0 + 2u;
    tf_round(x0,x1,13); tf_round(x0,x1,15); tf_round(x0,x1,26); tf_round(x0,x1,6);
    x0 += k0; x1 += k1 + 3u;
    tf_round(x0,x1,17); tf_round(x0,x1,29); tf_round(x0,x1,16); tf_round(x0,x1,24);
    x0 += k1; x1 += k2 + 4u;
    tf_round(x0,x1,13); tf_round(x0,x1,15); tf_round(x0,x1,26); tf_round(x0,x1,6);
    x0 += k2; x1 += k0 + 5u;
    return make_uint2(x0, x1);
}
__device__ __forceinline__ float gumbel_at(int lin) {
    uint2 r = threefry01(0u, (uint32_t)lin);    // partitionable mode
    uint32_t bits = r.x ^ r.y;
    float f = __uint_as_float((bits >> 9) | 0x3F800000u) - 1.0f;
    float u = fmaxf(1.17549435e-38f, f);
    return -logf(-logf(u));
}

// ------------------------------- K1 ----------------------------------------
__global__ __launch_bounds__(256) void k_mean_part(const float4* __restrict__ ts) {
    float s = 0.0f;
    const int n4 = (jme::B * jme::NITEMS) / 4;
    for (int i = blockIdx.x * blockDim.x + threadIdx.x; i < n4; i += gridDim.x * blockDim.x) {
        float4 v = ts[i];
        s += (v.x + v.y) + (v.z + v.w);
    }
    __shared__ float red[256];
    red[threadIdx.x] = s; __syncthreads();
    for (int o = 128; o > 0; o >>= 1) {
        if (threadIdx.x < o) red[threadIdx.x] += red[threadIdx.x + o];
        __syncthreads();
    }
    if (threadIdx.x == 0) g_tpart[blockIdx.x] = red[0];
}
__global__ __launch_bounds__(256) void k_mean_final() {
    __shared__ float red[256];
    red[threadIdx.x] = g_tpart[threadIdx.x]; __syncthreads();
    for (int o = 128; o > 0; o >>= 1) {
        if (threadIdx.x < o) red[threadIdx.x] += red[threadIdx.x + o];
        __syncthreads();
    }
    if (threadIdx.x == 0) g_t = red[0] / (float)(jme::B * jme::NITEMS);
}

// ------------------------------- K2: stable top-100 ------------------------
__device__ __forceinline__ uint32_t f2key(float f) {
    uint32_t u = __float_as_uint(f);
    return (u & 0x80000000u) ? ~u : (u | 0x80000000u);
}
__device__ __forceinline__ float key2f(uint32_t k) {
    uint32_t fb = (k & 0x80000000u) ? (k ^ 0x80000000u) : ~k;
    return __uint_as_float(fb);
}

__global__ __launch_bounds__(256) void k_topk(const float* __restrict__ pred,
                                              const int*   __restrict__ item_groups) {
    __shared__ unsigned long long cand[jme::CAND];   // 2 KB
    __shared__ uint32_t hist[256];                   // fallback only
    __shared__ int s_cnt;
    __shared__ uint32_t s_prefix;
    __shared__ int s_rem;

    const int row = blockIdx.x, tid = threadIdx.x;
    const float4* rp4 = (const float4*)(pred + (size_t)row * jme::NITEMS);
    constexpr int N4 = jme::NITEMS / 4;              // 2500

    for (int i = tid; i < jme::CAND; i += 256) cand[i] = 0xFFFFFFFFFFFFFFFFULL;
    if (tid == 0) s_cnt = 0;
    __syncthreads();

    // --- fast path: fixed threshold gather (N(0,1): E[count]=178, sd=13) ---
    const float THR = 2.10f;
    for (int c = tid; c < N4; c += 256) {
        float4 v = rp4[c];
        const float vv[4] = {v.x, v.y, v.z, v.w};
        #pragma unroll
        for (int e = 0; e < 4; ++e) {
            if (vv[e] > THR) {
                int pos = atomicAdd(&s_cnt, 1);
                if (pos < jme::CAND)
                    cand[pos] = (((unsigned long long)(~f2key(vv[e]))) << 32)
                              | (uint32_t)(4 * c + e);
            }
        }
    }
    __syncthreads();

    // --- exact fallback (statistically never taken; keeps correctness) ----
    if (s_cnt < jme::TOPK || s_cnt > jme::CAND) {
        const float* rp = pred + (size_t)row * jme::NITEMS;
        if (tid == 0) { s_rem = jme::TOPK; s_prefix = 0u; }
        __syncthreads();
        uint32_t prefix = 0u;
        for (int shift = 24; shift >= 0; shift -= 8) {
            for (int i = tid; i < 256; i += 256) hist[i] = 0u;
            __syncthreads();
            const uint32_t himask = (shift == 24) ? 0u : (0xFFFFFFFFu << (shift + 8));
            for (int i = tid; i < jme::NITEMS; i += 256) {
                uint32_t k = f2key(rp[i]);
                if ((k & himask) == prefix)
                    atomicAdd(&hist[(k >> shift) & 0xFF], 1u);
            }
            __syncthreads();
            if (tid == 0) {
                int cum = 0, sel = 0;
                for (int b = 255; b >= 0; --b) {
                    int h = (int)hist[b];
                    if (cum + h >= s_rem) { sel = b; s_rem -= cum; break; }
                    cum += h;
                }
                s_prefix = prefix | ((uint32_t)sel << shift);
            }
            __syncthreads();
            prefix = s_prefix;
            __syncthreads();
        }
        const uint32_t T = prefix;   // exact 100th-largest key
        for (int i = tid; i < jme::CAND; i += 256) cand[i] = 0xFFFFFFFFFFFFFFFFULL;
        if (tid == 0) s_cnt = 0;
        __syncthreads();
        for (int i = tid; i < jme::NITEMS; i += 256) {
            uint32_t k = f2key(rp[i]);
            if (k >= T) {
                int pos = atomicAdd(&s_cnt, 1);
                if (pos < jme::CAND)
                    cand[pos] = (((unsigned long long)(~k)) << 32) | (uint32_t)i;
            }
        }
        __syncthreads();
    }

    // bitonic sort 256 u64 ascending: (~key, idx) asc == (value desc, idx asc)
    #pragma unroll
    for (int kk = 2; kk <= jme::CAND; kk <<= 1) {
        for (int j = kk >> 1; j > 0; j >>= 1) {
            int i = tid, ixj = i ^ j;
            if (ixj > i) {
                unsigned long long a = cand[i], b = cand[ixj];
                bool asc = ((i & kk) == 0);
                if (asc ? (a > b) : (a < b)) { cand[i] = b; cand[ixj] = a; }
            }
            __syncthreads();
        }
    }

    if (tid < jme::TOPK) {
        unsigned long long e = cand[tid];
        uint32_t idx = (uint32_t)e;
        uint32_t key = ~(uint32_t)(e >> 32);
        g_topk_val[row * jme::TOPK + tid] = key2f(key);
        g_topk_grp[row * jme::TOPK + tid] = item_groups[idx];
    }
}

// ------------------------------- K3: exposure ------------------------------
// sigmoid((vi-vj)*10) = 0.5 + 0.5*tanh((vi-vj)*5)  -> 1 MUFU per pair
__global__ __launch_bounds__(128) void k_exposure() {
    const int b = blockIdx.x, tid = threadIdx.x;
    __shared__ float sval[jme::TOPK];
    __shared__ float nz[jme::NS][jme::TOPK];   // noisy * 5
    __shared__ float expo_sb[jme::NTASK];
    __shared__ float sdelta[jme::TOPK];
    __shared__ int   s_ig[jme::TOPK];

    const float t = g_t;
    if (tid < jme::TOPK) {
        sval[tid] = g_topk_val[b * jme::TOPK + tid];
        s_ig[tid] = g_topk_grp[b * jme::TOPK + tid];
    }
    __syncthreads();

    for (int tk = tid; tk < jme::NTASK; tk += 128) {
        int s = tk / jme::TOPK, i = tk - s * jme::TOPK;
        int lin = (s * jme::B + b) * jme::TOPK + i;
        nz[s][i] = (sval[i] + gumbel_at(lin)) * 5.0f;
    }
    __syncthreads();

    const float L2G = -0.3219280948873623f;     // log2(0.8)
    for (int tk = tid; tk < jme::NTASK; tk += 128) {
        int s = tk / jme::TOPK, i = tk - s * jme::TOPK;
        const float* rowp = nz[s];
        const float vi = rowp[i];
        float t0 = 0.0f, t1 = 0.0f, t2 = 0.0f, t3 = 0.0f;
        #pragma unroll 2
        for (int j = 0; j < jme::TOPK; j += 4) {
            float a0, a1, a2, a3;
            asm("tanh.approx.f32 %0, %1;" : "=f"(a0) : "f"(vi - rowp[j]));
            asm("tanh.approx.f32 %0, %1;" : "=f"(a1) : "f"(vi - rowp[j + 1]));
            asm("tanh.approx.f32 %0, %1;" : "=f"(a2) : "f"(vi - rowp[j + 2]));
            asm("tanh.approx.f32 %0, %1;" : "=f"(a3) : "f"(vi - rowp[j + 3]));
            t0 += a0; t1 += a1; t2 += a2; t3 += a3;
        }
        // rank-1 = 49.5 + 0.5*T ;  exposure = 2^((rank-1)*log2(gamma))
        float T = (t0 + t1) + (t2 + t3);
        float ex;
        asm("ex2.approx.f32 %0, %1;" : "=f"(ex) : "f"(fmaf(T, 0.5f * L2G, 49.5f * L2G)));
        expo_sb[tk] = ex;
    }
    __syncthreads();

    if (tid < jme::TOPK) {
        float acc = 0.0f;
        #pragma unroll
        for (int s = 0; s < jme::NS; ++s) acc += expo_sb[s * jme::TOPK + tid];
        sdelta[tid] = acc * 0.1f - t;
    }
    __syncthreads();

    if (tid == 0) {
        float ii = 0.0f;
        for (int i = 0; i < jme::TOPK; ++i) ii += sdelta[i] * sdelta[i];
        g_row_ii[b] = ii;
    }
    if (tid < jme::NIG) {
        float sD = 0.0f, c = 0.0f;
        for (int i = 0; i < jme::TOPK; ++i)
            if (s_ig[i] == tid) { sD += sdelta[i]; c += 1.0f; }
        g_grpD[b * jme::NIG + tid] = sD;
        g_grpC[b * jme::NIG + tid] = c;
    }
}

// ------------------------------- K4 ----------------------------------------
__global__ __launch_bounds__(256) void k_final(const int* __restrict__ user_groups,
                                               float* __restrict__ out) {
    __shared__ float red[256];
    const int tid = threadIdx.x;

    float s = 0.0f;
    for (int r = tid; r < jme::B; r += 256) s += g_row_ii[r];
    red[tid] = s; __syncthreads();
    for (int o = 128; o > 0; o >>= 1) {
        if (tid < o) red[tid] += red[tid + o];
        __syncthreads();
    }
    const float ii = red[0] / (float)(jme::B * jme::TOPK);
    __syncthreads();

    float a2 = 0.0f;
    if (tid < jme::NPAIR) {
        const int ug = tid / jme::NIG, ig = tid % jme::NIG;
        float sD = 0.0f, c = 0.0f;
        for (int r = 0; r < jme::B; ++r) {
            if (user_groups[r] == ug) {
                sD += g_grpD[r * jme::NIG + ig];
                c  += g_grpC[r * jme::NIG + ig];
            }
        }
        float avg = (c > 0.0f) ? (sD / fmaxf(c, 1.0f)) : 0.0f;
        a2 = avg * avg;
    }
    red[tid] = a2; __syncthreads();
    for (int o = 128; o > 0; o >>= 1) {
        if (tid < o) red[tid] += red[tid + o];
        __syncthreads();
    }
    const float gg = red[0] / (float)jme::NPAIR;

    if (tid == 0) {
        out[0] = ii + gg;
        out[1] = ii;
        out[2] = gg;
    }
}

// ------------------------------- launch ------------------------------------
extern "C" void kernel_launch(void* const* d_in, const int* in_sizes, int n_in,
                              void* d_out, int out_size) {
    const float* pred  = (const float*)d_in[0];
    const float* truth = (const float*)d_in[1];
    const int*   ug    = (const int*)  d_in[2];
    const int*   ig    = (const int*)  d_in[3];
    float* out = (float*)d_out;

    k_mean_part <<<256, 256>>>((const float4*)truth);
    k_mean_final<<<1,   256>>>();
    k_topk      <<<jme::B, 256>>>(pred, ig);
    k_exposure  <<<jme::B, 128>>>();
    k_final     <<<1,   256>>>(ug, out);
}

// round 4
// speedup vs baseline: 2.7719x; 1.0816x over previous
#include <cuda_runtime.h>
#include <stdint.h>

// ============================================================================
// JMEFairnessLoss:
//   K1  : partial sums of true_scores  (mean -> target exposure)
//   K1b : finalize mean -> g_t
//   KR  : FUSED per-row kernel: threshold-gather top-100 (rank-by-count,
//         exact radix fallback) + gumbel soft-rank exposure + row partials
//   K4  : final deterministic reductions -> (total, ii, gg)
// ============================================================================

namespace jme {
constexpr int B      = 1024;
constexpr int NITEMS = 10000;
constexpr int TOPK   = 100;
constexpr int NS     = 10;
constexpr int NIG    = 16;
constexpr int NPAIR  = 128;
constexpr int NTASK  = NS * TOPK;     // 1000
constexpr int CAND   = 256;
}

// ------------------------------- scratch -----------------------------------
__device__ float g_tpart[256];
__device__ float g_t;
__device__ float g_row_ii[jme::B];
__device__ float g_grpD[jme::B * jme::NIG];
__device__ float g_grpC[jme::B * jme::NIG];

// ------------------------------- threefry2x32 (JAX-exact, key=(0,1)) -------
__device__ __forceinline__ void tf_round(uint32_t& x0, uint32_t& x1, int r) {
    x0 += x1;
    x1 = __funnelshift_l(x1, x1, r);
    x1 ^= x0;
}
__device__ __forceinline__ uint2 threefry01(uint32_t x0, uint32_t x1) {
    const uint32_t k0 = 0u, k1 = 1u, k2 = 0x1BD11BDBu;
    x0 += k0; x1 += k1;
    tf_round(x0,x1,13); tf_round(x0,x1,15); tf_round(x0,x1,26); tf_round(x0,x1,6);
    x0 += k1; x1 += k2 + 1u;
    tf_round(x0,x1,17); tf_round(x0,x1,29); tf_round(x0,x1,16); tf_round(x0,x1,24);
    x0 += k2; x1 += k0 + 2u;
    tf_round(x0,x1,13); tf_round(x0,x1,15); tf_round(x0,x1,26); tf_round(x0,x1,6);
    x0 += k0; x1 += k1 + 3u;
    tf_round(x0,x1,17); tf_round(x0,x1,29); tf_round(x0,x1,16); tf_round(x0,x1,24);
    x0 += k1; x1 += k2 + 4u;
    tf_round(x0,x1,13); tf_round(x0,x1,15); tf_round(x0,x1,26); tf_round(x0,x1,6);
    x0 += k2; x1 += k0 + 5u;
    return make_uint2(x0, x1);
}
__device__ __forceinline__ float gumbel_at(int lin) {
    uint2 r = threefry01(0u, (uint32_t)lin);
    uint32_t bits = r.x ^ r.y;
    float f = __uint_as_float((bits >> 9) | 0x3F800000u) - 1.0f;
    float u = fmaxf(1.17549435e-38f, f);
    return -__logf(-__logf(u));
}

// ------------------------------- K1 ----------------------------------------
__global__ __launch_bounds__(256) void k_mean_part(const float4* __restrict__ ts) {
    float s = 0.0f;
    const int n4 = (jme::B * jme::NITEMS) / 4;
    for (int i = blockIdx.x * blockDim.x + threadIdx.x; i < n4; i += gridDim.x * blockDim.x) {
        float4 v = ts[i];
        s += (v.x + v.y) + (v.z + v.w);
    }
    __shared__ float red[256];
    red[threadIdx.x] = s; __syncthreads();
    for (int o = 128; o > 0; o >>= 1) {
        if (threadIdx.x < o) red[threadIdx.x] += red[threadIdx.x + o];
        __syncthreads();
    }
    if (threadIdx.x == 0) g_tpart[blockIdx.x] = red[0];
}
__global__ __launch_bounds__(256) void k_mean_final() {
    __shared__ float red[256];
    red[threadIdx.x] = g_tpart[threadIdx.x]; __syncthreads();
    for (int o = 128; o > 0; o >>= 1) {
        if (threadIdx.x < o) red[threadIdx.x] += red[threadIdx.x + o];
        __syncthreads();
    }
    if (threadIdx.x == 0) g_t = red[0] / (float)(jme::B * jme::NITEMS);
}

// ------------------------------- key helpers -------------------------------
__device__ __forceinline__ uint32_t f2key(float f) {
    uint32_t u = __float_as_uint(f);
    return (u & 0x80000000u) ? ~u : (u | 0x80000000u);
}
__device__ __forceinline__ float key2f(uint32_t k) {
    uint32_t fb = (k & 0x80000000u) ? (k ^ 0x80000000u) : ~k;
    return __uint_as_float(fb);
}

// ------------------------------- KR: fused row kernel ----------------------
__global__ __launch_bounds__(256) void k_row(const float* __restrict__ pred,
                                             const int*   __restrict__ item_groups) {
    __shared__ unsigned long long cand[jme::CAND];   // 2 KB
    __shared__ float sval[jme::TOPK];
    __shared__ int   s_ig[jme::TOPK];
    __shared__ float nz[jme::NS][jme::TOPK];         // noisy * 5
    __shared__ float expo_sb[jme::NTASK];            // 4 KB (hist aliased)
    __shared__ float sdelta[jme::TOPK];
    __shared__ int s_cnt;
    __shared__ uint32_t s_prefix;
    __shared__ int s_rem;
    uint32_t* hist = (uint32_t*)expo_sb;             // fallback-only alias

    const int row = blockIdx.x, tid = threadIdx.x;
    const float4* rp4 = (const float4*)(pred + (size_t)row * jme::NITEMS);
    constexpr int N4 = jme::NITEMS / 4;              // 2500

    // ---------------- phase A: top-100 ------------------------------------
    cand[tid] = 0ULL;
    if (tid == 0) s_cnt = 0;
    __syncthreads();

    // fast path: threshold gather; N(0,1) gives E[count]=178, sd=13
    const float THR = 2.10f;
    #pragma unroll 5
    for (int c = tid; c < N4; c += 256) {
        float4 v = rp4[c];
        const float vv[4] = {v.x, v.y, v.z, v.w};
        #pragma unroll
        for (int e = 0; e < 4; ++e) {
            if (vv[e] > THR) {
                int pos = atomicAdd(&s_cnt, 1);
                if (pos < jme::CAND)
                    cand[pos] = (((unsigned long long)f2key(vv[e])) << 32)
                              | (uint32_t)(0xFFFFFFFFu - (uint32_t)(4 * c + e));
            }
        }
    }
    __syncthreads();

    // exact fallback (statistically never taken; correctness for any input)
    if (s_cnt < jme::TOPK || s_cnt > jme::CAND) {
        const float* rp = pred + (size_t)row * jme::NITEMS;
        if (tid == 0) { s_rem = jme::TOPK; s_prefix = 0u; }
        __syncthreads();
        uint32_t prefix = 0u;
        for (int shift = 24; shift >= 0; shift -= 8) {
            hist[tid] = 0u;
            __syncthreads();
            const uint32_t himask = (shift == 24) ? 0u : (0xFFFFFFFFu << (shift + 8));
            for (int i = tid; i < jme::NITEMS; i += 256) {
                uint32_t k = f2key(rp[i]);
                if ((k & himask) == prefix)
                    atomicAdd(&hist[(k >> shift) & 0xFF], 1u);
            }
            __syncthreads();
            if (tid == 0) {
                int cum = 0, sel = 0;
                for (int b = 255; b >= 0; --b) {
                    int h = (int)hist[b];
                    if (cum + h >= s_rem) { sel = b; s_rem -= cum; break; }
                    cum += h;
                }
                s_prefix = prefix | ((uint32_t)sel << shift);
            }
            __syncthreads();
            prefix = s_prefix;
            __syncthreads();
        }
        const uint32_t T = prefix;   // exact 100th-largest key
        cand[tid] = 0ULL;
        if (tid == 0) s_cnt = 0;
        __syncthreads();
        for (int i = tid; i < jme::NITEMS; i += 256) {
            uint32_t k = f2key(rp[i]);
            if (k >= T) {
                int pos = atomicAdd(&s_cnt, 1);
                if (pos < jme::CAND)
                    cand[pos] = (((unsigned long long)k) << 32)
                              | (uint32_t)(0xFFFFFFFFu - (uint32_t)i);
            }
        }
        __syncthreads();
    }

    // rank-by-count: rank = #{j : cand[j] > cand[i]}; scatter top-100
    {
        unsigned long long e = cand[tid];
        int r = 0;
        #pragma unroll 8
        for (int j = 0; j < jme::CAND; ++j) r += (cand[j] > e);
        if (e != 0ULL && r < jme::TOPK) {
            sval[r] = key2f((uint32_t)(e >> 32));
            s_ig[r] = item_groups[0xFFFFFFFFu - (uint32_t)e];
        }
    }
    __syncthreads();

    // ---------------- phase B: exposure -----------------------------------
    const float t = g_t;
    for (int tk = tid; tk < jme::NTASK; tk += 256) {
        int s = tk / jme::TOPK, i = tk - s * jme::TOPK;
        int lin = (s * jme::B + row) * jme::TOPK + i;
        nz[s][i] = (sval[i] + gumbel_at(lin)) * 5.0f;
    }
    __syncthreads();

    const float L2G = -0.3219280948873623f;     // log2(0.8)
    for (int tk = tid; tk < jme::NTASK; tk += 256) {
        int s = tk / jme::TOPK, i = tk - s * jme::TOPK;
        const float* rowp = nz[s];
        const float vi = rowp[i];
        float t0 = 0.0f, t1 = 0.0f, t2 = 0.0f, t3 = 0.0f;
        #pragma unroll 5
        for (int j = 0; j < jme::TOPK; j += 4) {
            float a0, a1, a2, a3;
            asm("tanh.approx.f32 %0, %1;" : "=f"(a0) : "f"(vi - rowp[j]));
            asm("tanh.approx.f32 %0, %1;" : "=f"(a1) : "f"(vi - rowp[j + 1]));
            asm("tanh.approx.f32 %0, %1;" : "=f"(a2) : "f"(vi - rowp[j + 2]));
            asm("tanh.approx.f32 %0, %1;" : "=f"(a3) : "f"(vi - rowp[j + 3]));
            t0 += a0; t1 += a1; t2 += a2; t3 += a3;
        }
        float T = (t0 + t1) + (t2 + t3);
        float ex;
        asm("ex2.approx.f32 %0, %1;" : "=f"(ex) : "f"(fmaf(T, 0.5f * L2G, 49.5f * L2G)));
        expo_sb[tk] = ex;
    }
    __syncthreads();

    if (tid < jme::TOPK) {
        float acc = 0.0f;
        #pragma unroll
        for (int s = 0; s < jme::NS; ++s) acc += expo_sb[s * jme::TOPK + tid];
        sdelta[tid] = acc * 0.1f - t;
    }
    __syncthreads();

    if (tid == 0) {
        float ii = 0.0f;
        for (int i = 0; i < jme::TOPK; ++i) ii += sdelta[i] * sdelta[i];
        g_row_ii[row] = ii;
    }
    if (tid < jme::NIG) {
        float sD = 0.0f, c = 0.0f;
        for (int i = 0; i < jme::TOPK; ++i)
            if (s_ig[i] == tid) { sD += sdelta[i]; c += 1.0f; }
        g_grpD[row * jme::NIG + tid] = sD;
        g_grpC[row * jme::NIG + tid] = c;
    }
}

// ------------------------------- K4 ----------------------------------------
__global__ __launch_bounds__(256) void k_final(const int* __restrict__ user_groups,
                                               float* __restrict__ out) {
    __shared__ float red[256];
    const int tid = threadIdx.x;

    float s = 0.0f;
    for (int r = tid; r < jme::B; r += 256) s += g_row_ii[r];
    red[tid] = s; __syncthreads();
    for (int o = 128; o > 0; o >>= 1) {
        if (tid < o) red[tid] += red[tid + o];
        __syncthreads();
    }
    const float ii = red[0] / (float)(jme::B * jme::TOPK);
    __syncthreads();

    float a2 = 0.0f;
    if (tid < jme::NPAIR) {
        const int ug = tid / jme::NIG, ig = tid % jme::NIG;
        float sD = 0.0f, c = 0.0f;
        for (int r = 0; r < jme::B; ++r) {
            if (user_groups[r] == ug) {
                sD += g_grpD[r * jme::NIG + ig];
                c  += g_grpC[r * jme::NIG + ig];
            }
        }
        float avg = (c > 0.0f) ? (sD / fmaxf(c, 1.0f)) : 0.0f;
        a2 = avg * avg;
    }
    red[tid] = a2; __syncthreads();
    for (int o = 128; o > 0; o >>= 1) {
        if (tid < o) red[tid] += red[tid + o];
        __syncthreads();
    }
    const float gg = red[0] / (float)jme::NPAIR;

    if (tid == 0) {
        out[0] = ii + gg;
        out[1] = ii;
        out[2] = gg;
    }
}

// ------------------------------- launch ------------------------------------
extern "C" void kernel_launch(void* const* d_in, const int* in_sizes, int n_in,
                              void* d_out, int out_size) {
    const float* pred  = (const float*)d_in[0];
    const float* truth = (const float*)d_in[1];
    const int*   ug    = (const int*)  d_in[2];
    const int*   ig    = (const int*)  d_in[3];
    float* out = (float*)d_out;

    k_mean_part <<<256, 256>>>((const float4*)truth);
    k_mean_final<<<1,   256>>>();
    k_row       <<<jme::B, 256>>>(pred, ig);
    k_final     <<<1,   256>>>(ug, out);
}

// round 5
// speedup vs baseline: 4.9065x; 1.7701x over previous
#include <cuda_runtime.h>
#include <stdint.h>

// ============================================================================
// JMEFairnessLoss:
//   K1  : partial sums of true_scores  (mean -> target exposure)
//   K1b : finalize mean -> g_t
//   KR  : FUSED per-row kernel: threshold-gather top-100 (rank-by-count,
//         exact radix fallback) + gumbel soft-rank exposure + row partials
//   KP  : grid=129 parallel epilogue: per-(ug,ig) pair avg^2 + ii row-sum
//   KF  : 1-block combine -> (total, ii, gg)
// ============================================================================

namespace jme {
constexpr int B      = 1024;
constexpr int NITEMS = 10000;
constexpr int TOPK   = 100;
constexpr int NS     = 10;
constexpr int NIG    = 16;
constexpr int NUG    = 8;
constexpr int NPAIR  = 128;
constexpr int NTASK  = NS * TOPK;     // 1000
constexpr int CAND   = 256;
}

// ------------------------------- scratch -----------------------------------
__device__ float g_tpart[256];
__device__ float g_t;
__device__ float g_row_ii[jme::B];
__device__ float g_grpD[jme::NIG * jme::B];   // TRANSPOSED: [ig][row]
__device__ float g_grpC[jme::NIG * jme::B];
__device__ float g_pair[jme::NPAIR];
__device__ float g_ii_sum;

// ------------------------------- threefry2x32 (JAX-exact, key=(0,1)) -------
__device__ __forceinline__ void tf_round(uint32_t& x0, uint32_t& x1, int r) {
    x0 += x1;
    x1 = __funnelshift_l(x1, x1, r);
    x1 ^= x0;
}
__device__ __forceinline__ uint2 threefry01(uint32_t x0, uint32_t x1) {
    const uint32_t k0 = 0u, k1 = 1u, k2 = 0x1BD11BDBu;
    x0 += k0; x1 += k1;
    tf_round(x0,x1,13); tf_round(x0,x1,15); tf_round(x0,x1,26); tf_round(x0,x1,6);
    x0 += k1; x1 += k2 + 1u;
    tf_round(x0,x1,17); tf_round(x0,x1,29); tf_round(x0,x1,16); tf_round(x0,x1,24);
    x0 += k2; x1 += k0 + 2u;
    tf_round(x0,x1,13); tf_round(x0,x1,15); tf_round(x0,x1,26); tf_round(x0,x1,6);
    x0 += k0; x1 += k1 + 3u;
    tf_round(x0,x1,17); tf_round(x0,x1,29); tf_round(x0,x1,16); tf_round(x0,x1,24);
    x0 += k1; x1 += k2 + 4u;
    tf_round(x0,x1,13); tf_round(x0,x1,15); tf_round(x0,x1,26); tf_round(x0,x1,6);
    x0 += k2; x1 += k0 + 5u;
    return make_uint2(x0, x1);
}
__device__ __forceinline__ float gumbel_at(int lin) {
    uint2 r = threefry01(0u, (uint32_t)lin);
    uint32_t bits = r.x ^ r.y;
    float f = __uint_as_float((bits >> 9) | 0x3F800000u) - 1.0f;
    float u = fmaxf(1.17549435e-38f, f);
    return -__logf(-__logf(u));
}

// ------------------------------- K1 ----------------------------------------
__global__ __launch_bounds__(256) void k_mean_part(const float4* __restrict__ ts) {
    float s = 0.0f;
    const int n4 = (jme::B * jme::NITEMS) / 4;
    for (int i = blockIdx.x * blockDim.x + threadIdx.x; i < n4; i += gridDim.x * blockDim.x) {
        float4 v = ts[i];
        s += (v.x + v.y) + (v.z + v.w);
    }
    __shared__ float red[256];
    red[threadIdx.x] = s; __syncthreads();
    for (int o = 128; o > 0; o >>= 1) {
        if (threadIdx.x < o) red[threadIdx.x] += red[threadIdx.x + o];
        __syncthreads();
    }
    if (threadIdx.x == 0) g_tpart[blockIdx.x] = red[0];
}
__global__ __launch_bounds__(256) void k_mean_final() {
    __shared__ float red[256];
    red[threadIdx.x] = g_tpart[threadIdx.x]; __syncthreads();
    for (int o = 128; o > 0; o >>= 1) {
        if (threadIdx.x < o) red[threadIdx.x] += red[threadIdx.x + o];
        __syncthreads();
    }
    if (threadIdx.x == 0) g_t = red[0] / (float)(jme::B * jme::NITEMS);
}

// ------------------------------- key helpers -------------------------------
__device__ __forceinline__ uint32_t f2key(float f) {
    uint32_t u = __float_as_uint(f);
    return (u & 0x80000000u) ? ~u : (u | 0x80000000u);
}
__device__ __forceinline__ float key2f(uint32_t k) {
    uint32_t fb = (k & 0x80000000u) ? (k ^ 0x80000000u) : ~k;
    return __uint_as_float(fb);
}

// ------------------------------- KR: fused row kernel ----------------------
__global__ __launch_bounds__(256) void k_row(const float* __restrict__ pred,
                                             const int*   __restrict__ item_groups) {
    __shared__ unsigned long long cand[jme::CAND];   // 2 KB
    __shared__ float sval[jme::TOPK];
    __shared__ int   s_ig[jme::TOPK];
    __shared__ float nz[jme::NS][jme::TOPK];         // noisy * 5
    __shared__ float expo_sb[jme::NTASK];            // 4 KB (hist aliased)
    __shared__ float sdelta[jme::TOPK];
    __shared__ int s_cnt;
    __shared__ uint32_t s_prefix;
    __shared__ int s_rem;
    uint32_t* hist = (uint32_t*)expo_sb;             // fallback-only alias

    const int row = blockIdx.x, tid = threadIdx.x;
    const float4* rp4 = (const float4*)(pred + (size_t)row * jme::NITEMS);
    constexpr int N4 = jme::NITEMS / 4;              // 2500

    // ---------------- phase A: top-100 ------------------------------------
    cand[tid] = 0ULL;
    if (tid == 0) s_cnt = 0;
    __syncthreads();

    // fast path: threshold gather; N(0,1) gives E[count]=178, sd=13
    const float THR = 2.10f;
    #pragma unroll 5
    for (int c = tid; c < N4; c += 256) {
        float4 v = rp4[c];
        const float vv[4] = {v.x, v.y, v.z, v.w};
        #pragma unroll
        for (int e = 0; e < 4; ++e) {
            if (vv[e] > THR) {
                int pos = atomicAdd(&s_cnt, 1);
                if (pos < jme::CAND)
                    cand[pos] = (((unsigned long long)f2key(vv[e])) << 32)
                              | (uint32_t)(0xFFFFFFFFu - (uint32_t)(4 * c + e));
            }
        }
    }
    __syncthreads();

    // exact fallback (statistically never taken; correctness for any input)
    if (s_cnt < jme::TOPK || s_cnt > jme::CAND) {
        const float* rp = pred + (size_t)row * jme::NITEMS;
        if (tid == 0) { s_rem = jme::TOPK; s_prefix = 0u; }
        __syncthreads();
        uint32_t prefix = 0u;
        for (int shift = 24; shift >= 0; shift -= 8) {
            hist[tid] = 0u;
            __syncthreads();
            const uint32_t himask = (shift == 24) ? 0u : (0xFFFFFFFFu << (shift + 8));
            for (int i = tid; i < jme::NITEMS; i += 256) {
                uint32_t k = f2key(rp[i]);
                if ((k & himask) == prefix)
                    atomicAdd(&hist[(k >> shift) & 0xFF], 1u);
            }
            __syncthreads();
            if (tid == 0) {
                int cum = 0, sel = 0;
                for (int b = 255; b >= 0; --b) {
                    int h = (int)hist[b];
                    if (cum + h >= s_rem) { sel = b; s_rem -= cum; break; }
                    cum += h;
                }
                s_prefix = prefix | ((uint32_t)sel << shift);
            }
            __syncthreads();
            prefix = s_prefix;
            __syncthreads();
        }
        const uint32_t T = prefix;   // exact 100th-largest key
        cand[tid] = 0ULL;
        if (tid == 0) s_cnt = 0;
        __syncthreads();
        for (int i = tid; i < jme::NITEMS; i += 256) {
            uint32_t k = f2key(rp[i]);
            if (k >= T) {
                int pos = atomicAdd(&s_cnt, 1);
                if (pos < jme::CAND)
                    cand[pos] = (((unsigned long long)k) << 32)
                              | (uint32_t)(0xFFFFFFFFu - (uint32_t)i);
            }
        }
        __syncthreads();
    }

    // rank-by-count: rank = #{j : cand[j] > cand[i]}; scatter top-100
    {
        unsigned long long e = cand[tid];
        int r = 0;
        #pragma unroll 8
        for (int j = 0; j < jme::CAND; ++j) r += (cand[j] > e);
        if (e != 0ULL && r < jme::TOPK) {
            sval[r] = key2f((uint32_t)(e >> 32));
            s_ig[r] = item_groups[0xFFFFFFFFu - (uint32_t)e];
        }
    }
    __syncthreads();

    // ---------------- phase B: exposure -----------------------------------
    const float t = g_t;
    for (int tk = tid; tk < jme::NTASK; tk += 256) {
        int s = tk / jme::TOPK, i = tk - s * jme::TOPK;
        int lin = (s * jme::B + row) * jme::TOPK + i;
        nz[s][i] = (sval[i] + gumbel_at(lin)) * 5.0f;
    }
    __syncthreads();

    const float L2G = -0.3219280948873623f;     // log2(0.8)
    for (int tk = tid; tk < jme::NTASK; tk += 256) {
        int s = tk / jme::TOPK, i = tk - s * jme::TOPK;
        const float* rowp = nz[s];
        const float vi = rowp[i];
        float t0 = 0.0f, t1 = 0.0f, t2 = 0.0f, t3 = 0.0f;
        #pragma unroll 5
        for (int j = 0; j < jme::TOPK; j += 4) {
            float a0, a1, a2, a3;
            asm("tanh.approx.f32 %0, %1;" : "=f"(a0) : "f"(vi - rowp[j]));
            asm("tanh.approx.f32 %0, %1;" : "=f"(a1) : "f"(vi - rowp[j + 1]));
            asm("tanh.approx.f32 %0, %1;" : "=f"(a2) : "f"(vi - rowp[j + 2]));
            asm("tanh.approx.f32 %0, %1;" : "=f"(a3) : "f"(vi - rowp[j + 3]));
            t0 += a0; t1 += a1; t2 += a2; t3 += a3;
        }
        float T = (t0 + t1) + (t2 + t3);
        float ex;
        asm("ex2.approx.f32 %0, %1;" : "=f"(ex) : "f"(fmaf(T, 0.5f * L2G, 49.5f * L2G)));
        expo_sb[tk] = ex;
    }
    __syncthreads();

    if (tid < jme::TOPK) {
        float acc = 0.0f;
        #pragma unroll
        for (int s = 0; s < jme::NS; ++s) acc += expo_sb[s * jme::TOPK + tid];
        sdelta[tid] = acc * 0.1f - t;
    }
    __syncthreads();

    if (tid == 0) {
        float ii = 0.0f;
        for (int i = 0; i < jme::TOPK; ++i) ii += sdelta[i] * sdelta[i];
        g_row_ii[row] = ii;
    }
    if (tid < jme::NIG) {
        float sD = 0.0f, c = 0.0f;
        for (int i = 0; i < jme::TOPK; ++i)
            if (s_ig[i] == tid) { sD += sdelta[i]; c += 1.0f; }
        g_grpD[tid * jme::B + row] = sD;      // transposed for coalesced KP
        g_grpC[tid * jme::B + row] = c;
    }
}

// ------------------------------- KP: parallel epilogue ----------------------
// blocks 0..127: pair (ug = p/16, ig = p%16) -> avg^2 ; block 128: sum(row_ii)
__global__ __launch_bounds__(256) void k_pair(const int* __restrict__ user_groups) {
    __shared__ float redD[256];
    __shared__ float redC[256];
    const int p = blockIdx.x, tid = threadIdx.x;

    if (p == jme::NPAIR) {
        float s = 0.0f;
        for (int r = tid; r < jme::B; r += 256) s += g_row_ii[r];
        redD[tid] = s; __syncthreads();
        for (int o = 128; o > 0; o >>= 1) {
            if (tid < o) redD[tid] += redD[tid + o];
            __syncthreads();
        }
        if (tid == 0) g_ii_sum = redD[0];
        return;
    }

    const int ug = p / jme::NIG, igc = p % jme::NIG;
    float sD = 0.0f, c = 0.0f;
    for (int r = tid; r < jme::B; r += 256) {
        if (user_groups[r] == ug) {
            sD += g_grpD[igc * jme::B + r];
            c  += g_grpC[igc * jme::B + r];
        }
    }
    redD[tid] = sD; redC[tid] = c; __syncthreads();
    for (int o = 128; o > 0; o >>= 1) {
        if (tid < o) { redD[tid] += redD[tid + o]; redC[tid] += redC[tid + o]; }
        __syncthreads();
    }
    if (tid == 0) {
        float cc = redC[0];
        float avg = (cc > 0.0f) ? (redD[0] / fmaxf(cc, 1.0f)) : 0.0f;
        g_pair[p] = avg * avg;
    }
}

// ------------------------------- KF: combine --------------------------------
__global__ __launch_bounds__(128) void k_final2(float* __restrict__ out) {
    __shared__ float red[128];
    const int tid = threadIdx.x;
    red[tid] = g_pair[tid]; __syncthreads();
    for (int o = 64; o > 0; o >>= 1) {
        if (tid < o) red[tid] += red[tid + o];
        __syncthreads();
    }
    if (tid == 0) {
        const float gg = red[0] / (float)jme::NPAIR;
        const float ii = g_ii_sum / (float)(jme::B * jme::TOPK);
        out[0] = ii + gg;
        out[1] = ii;
        out[2] = gg;
    }
}

// ------------------------------- launch ------------------------------------
extern "C" void kernel_launch(void* const* d_in, const int* in_sizes, int n_in,
                              void* d_out, int out_size) {
    const float* pred  = (const float*)d_in[0];
    const float* truth = (const float*)d_in[1];
    const int*   ug    = (const int*)  d_in[2];
    const int*   ig    = (const int*)  d_in[3];
    float* out = (float*)d_out;

    k_mean_part <<<256, 256>>>((const float4*)truth);
    k_mean_final<<<1,   256>>>();
    k_row       <<<jme::B, 256>>>(pred, ig);
    k_pair      <<<jme::NPAIR + 1, 256>>>(ug);
    k_final2    <<<1, 128>>>(out);
}

// round 6
// speedup vs baseline: 5.7123x; 1.1642x over previous
#include <cuda_runtime.h>
#include <stdint.h>

// ============================================================================
// JMEFairnessLoss — 2-kernel pipeline:
//   KR : per-row fused: truth-row sum + threshold top-100 (exact radix
//        fallback) + gumbel soft-rank exposure -> RAW row sums (t deferred)
//   KP : grid=129: per-(ug,ig) pair avg^2 (t applied) + ii sum; last-block
//        ticket finalizes -> (total, ii, gg)
// ============================================================================

namespace jme {
constexpr int B      = 1024;
constexpr int NITEMS = 10000;
constexpr int TOPK   = 100;
constexpr int NS     = 10;
constexpr int NIG    = 16;
constexpr int NPAIR  = 128;
constexpr int NTASK  = NS * TOPK;     // 1000
constexpr int CAND   = 256;
}

// ------------------------------- scratch -----------------------------------
__device__ float g_tpart[jme::B];              // per-row truth sums
__device__ float g_rowSq[jme::B];              // sum e^2 per row (raw)
__device__ float g_rowSl[jme::B];              // sum e   per row (raw)
__device__ float g_grpD[jme::NIG * jme::B];    // TRANSPOSED [ig][row], raw sum e
__device__ float g_grpC[jme::NIG * jme::B];    // counts
__device__ float g_pair[jme::NPAIR];
__device__ float g_ii_sum;
__device__ int   g_done = 0;

// ------------------------------- threefry2x32 (JAX-exact, key=(0,1)) -------
__device__ __forceinline__ void tf_round(uint32_t& x0, uint32_t& x1, int r) {
    x0 += x1;
    x1 = __funnelshift_l(x1, x1, r);
    x1 ^= x0;
}
__device__ __forceinline__ uint2 threefry01(uint32_t x0, uint32_t x1) {
    const uint32_t k0 = 0u, k1 = 1u, k2 = 0x1BD11BDBu;
    x0 += k0; x1 += k1;
    tf_round(x0,x1,13); tf_round(x0,x1,15); tf_round(x0,x1,26); tf_round(x0,x1,6);
    x0 += k1; x1 += k2 + 1u;
    tf_round(x0,x1,17); tf_round(x0,x1,29); tf_round(x0,x1,16); tf_round(x0,x1,24);
    x0 += k2; x1 += k0 + 2u;
    tf_round(x0,x1,13); tf_round(x0,x1,15); tf_round(x0,x1,26); tf_round(x0,x1,6);
    x0 += k0; x1 += k1 + 3u;
    tf_round(x0,x1,17); tf_round(x0,x1,29); tf_round(x0,x1,16); tf_round(x0,x1,24);
    x0 += k1; x1 += k2 + 4u;
    tf_round(x0,x1,13); tf_round(x0,x1,15); tf_round(x0,x1,26); tf_round(x0,x1,6);
    x0 += k2; x1 += k0 + 5u;
    return make_uint2(x0, x1);
}
__device__ __forceinline__ float gumbel_at(int lin) {
    uint2 r = threefry01(0u, (uint32_t)lin);
    uint32_t bits = r.x ^ r.y;
    float f = __uint_as_float((bits >> 9) | 0x3F800000u) - 1.0f;
    float u = fmaxf(1.17549435e-38f, f);
    return -__logf(-__logf(u));
}

// ------------------------------- key helpers -------------------------------
__device__ __forceinline__ uint32_t f2key(float f) {
    uint32_t u = __float_as_uint(f);
    return (u & 0x80000000u) ? ~u : (u | 0x80000000u);
}
__device__ __forceinline__ float key2f(uint32_t k) {
    uint32_t fb = (k & 0x80000000u) ? (k ^ 0x80000000u) : ~k;
    return __uint_as_float(fb);
}

// ------------------------------- KR: fused row kernel ----------------------
__global__ __launch_bounds__(256) void k_row(const float* __restrict__ pred,
                                             const float* __restrict__ truth,
                                             const int*   __restrict__ item_groups) {
    __shared__ unsigned long long cand[jme::CAND];   // 2 KB
    __shared__ float sval[jme::TOPK];
    __shared__ int   s_ig[jme::TOPK];
    __shared__ float nz[jme::NS][jme::TOPK];         // noisy * 5
    __shared__ float expo_sb[jme::NTASK];            // aliased: red / hist
    __shared__ float sdelta[jme::TOPK];              // raw e per item
    __shared__ int s_cnt;
    __shared__ uint32_t s_prefix;
    __shared__ int s_rem;
    float*    red  = expo_sb;                        // truth reduction alias
    uint32_t* hist = (uint32_t*)expo_sb;             // fallback alias

    const int row = blockIdx.x, tid = threadIdx.x;
    const float4* rp4 = (const float4*)(pred  + (size_t)row * jme::NITEMS);
    const float4* tr4 = (const float4*)(truth + (size_t)row * jme::NITEMS);
    constexpr int N4 = jme::NITEMS / 4;              // 2500

    // ---------------- phase A: truth row-sum + top-100 gather --------------
    cand[tid] = 0ULL;
    if (tid == 0) s_cnt = 0;
    __syncthreads();

    const float THR = 2.10f;   // N(0,1): E[count>THR]=178, sd=13 (cap 256)
    float tsum = 0.0f;
    #pragma unroll 5
    for (int c = tid; c < N4; c += 256) {
        float4 v  = rp4[c];
        float4 tv = tr4[c];
        tsum += (tv.x + tv.y) + (tv.z + tv.w);
        const float vv[4] = {v.x, v.y, v.z, v.w};
        #pragma unroll
        for (int e = 0; e < 4; ++e) {
            if (vv[e] > THR) {
                int pos = atomicAdd(&s_cnt, 1);
                if (pos < jme::CAND)
                    cand[pos] = (((unsigned long long)f2key(vv[e])) << 32)
                              | (uint32_t)(0xFFFFFFFFu - (uint32_t)(4 * c + e));
            }
        }
    }
    red[tid] = tsum;
    __syncthreads();
    for (int o = 128; o > 0; o >>= 1) {
        if (tid < o) red[tid] += red[tid + o];
        __syncthreads();
    }
    if (tid == 0) g_tpart[row] = red[0];
    __syncthreads();

    // exact fallback (statistically never taken; correctness for any input)
    if (s_cnt < jme::TOPK || s_cnt > jme::CAND) {
        const float* rp = pred + (size_t)row * jme::NITEMS;
        if (tid == 0) { s_rem = jme::TOPK; s_prefix = 0u; }
        __syncthreads();
        uint32_t prefix = 0u;
        for (int shift = 24; shift >= 0; shift -= 8) {
            hist[tid] = 0u;
            __syncthreads();
            const uint32_t himask = (shift == 24) ? 0u : (0xFFFFFFFFu << (shift + 8));
            for (int i = tid; i < jme::NITEMS; i += 256) {
                uint32_t k = f2key(rp[i]);
                if ((k & himask) == prefix)
                    atomicAdd(&hist[(k >> shift) & 0xFF], 1u);
            }
            __syncthreads();
            if (tid == 0) {
                int cum = 0, sel = 0;
                for (int b = 255; b >= 0; --b) {
                    int h = (int)hist[b];
                    if (cum + h >= s_rem) { sel = b; s_rem -= cum; break; }
                    cum += h;
                }
                s_prefix = prefix | ((uint32_t)sel << shift);
            }
            __syncthreads();
            prefix = s_prefix;
            __syncthreads();
        }
        const uint32_t T = prefix;   // exact 100th-largest key
        cand[tid] = 0ULL;
        if (tid == 0) s_cnt = 0;
        __syncthreads();
        for (int i = tid; i < jme::NITEMS; i += 256) {
            uint32_t k = f2key(rp[i]);
            if (k >= T) {
                int pos = atomicAdd(&s_cnt, 1);
                if (pos < jme::CAND)
                    cand[pos] = (((unsigned long long)k) << 32)
                              | (uint32_t)(0xFFFFFFFFu - (uint32_t)i);
            }
        }
        __syncthreads();
    }

    // rank-by-count: rank = #{j : cand[j] > cand[i]}; scatter top-100
    {
        unsigned long long e = cand[tid];
        int r = 0;
        #pragma unroll 8
        for (int j = 0; j < jme::CAND; ++j) r += (cand[j] > e);
        if (e != 0ULL && r < jme::TOPK) {
            sval[r] = key2f((uint32_t)(e >> 32));
            s_ig[r] = item_groups[0xFFFFFFFFu - (uint32_t)e];
        }
    }
    __syncthreads();

    // ---------------- phase B: exposure (raw, no t) -------------------------
    for (int tk = tid; tk < jme::NTASK; tk += 256) {
        int s = tk / jme::TOPK, i = tk - s * jme::TOPK;
        int lin = (s * jme::B + row) * jme::TOPK + i;
        nz[s][i] = (sval[i] + gumbel_at(lin)) * 5.0f;
    }
    __syncthreads();

    const float L2G = -0.3219280948873623f;     // log2(0.8)
    for (int tk = tid; tk < jme::NTASK; tk += 256) {
        int s = tk / jme::TOPK, i = tk - s * jme::TOPK;
        const float* rowp = nz[s];
        const float vi = rowp[i];
        float t0 = 0.0f, t1 = 0.0f, t2 = 0.0f, t3 = 0.0f;
        #pragma unroll 5
        for (int j = 0; j < jme::TOPK; j += 4) {
            float a0, a1, a2, a3;
            asm("tanh.approx.f32 %0, %1;" : "=f"(a0) : "f"(vi - rowp[j]));
            asm("tanh.approx.f32 %0, %1;" : "=f"(a1) : "f"(vi - rowp[j + 1]));
            asm("tanh.approx.f32 %0, %1;" : "=f"(a2) : "f"(vi - rowp[j + 2]));
            asm("tanh.approx.f32 %0, %1;" : "=f"(a3) : "f"(vi - rowp[j + 3]));
            t0 += a0; t1 += a1; t2 += a2; t3 += a3;
        }
        float T = (t0 + t1) + (t2 + t3);
        float ex;
        asm("ex2.approx.f32 %0, %1;" : "=f"(ex) : "f"(fmaf(T, 0.5f * L2G, 49.5f * L2G)));
        expo_sb[tk] = ex;
    }
    __syncthreads();

    if (tid < jme::TOPK) {
        float acc = 0.0f;
        #pragma unroll
        for (int s = 0; s < jme::NS; ++s) acc += expo_sb[s * jme::TOPK + tid];
        sdelta[tid] = acc * 0.1f;           // raw e_i (t deferred to KP)
    }
    __syncthreads();

    if (tid == 0) {
        float sq = 0.0f, sl = 0.0f;
        for (int i = 0; i < jme::TOPK; ++i) {
            float e = sdelta[i];
            sq += e * e; sl += e;
        }
        g_rowSq[row] = sq;
        g_rowSl[row] = sl;
    }
    if (tid < jme::NIG) {
        float sD = 0.0f, c = 0.0f;
        for (int i = 0; i < jme::TOPK; ++i)
            if (s_ig[i] == tid) { sD += sdelta[i]; c += 1.0f; }
        g_grpD[tid * jme::B + row] = sD;
        g_grpC[tid * jme::B + row] = c;
    }
}

// ------------------------------- KP: epilogue -------------------------------
// blocks 0..127: pair (ug,ig) -> avg^2 ; block 128: ii ; last ticket: combine
__global__ __launch_bounds__(256) void k_pair(const int* __restrict__ user_groups,
                                              float* __restrict__ out) {
    __shared__ float rA[256];
    __shared__ float rB[256];
    __shared__ float rT[256];
    __shared__ int s_ticket;
    const int p = blockIdx.x, tid = threadIdx.x;

    // every block reduces t-partials (deterministic, identical order)
    {
        float4 tp = ((const float4*)g_tpart)[tid];
        rT[tid] = (tp.x + tp.y) + (tp.z + tp.w);
    }

    float a = 0.0f, b = 0.0f;
    if (p < jme::NPAIR) {
        const int ug = p / jme::NIG, igc = p % jme::NIG;
        int4  u = ((const int4*)user_groups)[tid];
        float4 D = ((const float4*)(g_grpD + igc * jme::B))[tid];
        float4 C = ((const float4*)(g_grpC + igc * jme::B))[tid];
        if (u.x == ug) { a += D.x; b += C.x; }
        if (u.y == ug) { a += D.y; b += C.y; }
        if (u.z == ug) { a += D.z; b += C.z; }
        if (u.w == ug) { a += D.w; b += C.w; }
    } else {
        float4 q = ((const float4*)g_rowSq)[tid];
        float4 l = ((const float4*)g_rowSl)[tid];
        a = (q.x + q.y) + (q.z + q.w);
        b = (l.x + l.y) + (l.z + l.w);
    }
    rA[tid] = a; rB[tid] = b;
    __syncthreads();
    for (int o = 128; o > 0; o >>= 1) {
        if (tid < o) {
            rA[tid] += rA[tid + o];
            rB[tid] += rB[tid + o];
            rT[tid] += rT[tid + o];
        }
        __syncthreads();
    }

    if (tid == 0) {
        const float t = rT[0] / (float)(jme::B * jme::NITEMS);
        if (p < jme::NPAIR) {
            float D = rA[0], C = rB[0];
            float avg = (C > 0.0f) ? ((D - t * C) / fmaxf(C, 1.0f)) : 0.0f;
            g_pair[p] = avg * avg;
        } else {
            const float BK = (float)(jme::B * jme::TOPK);
            g_ii_sum = (rA[0] - 2.0f * t * rB[0] + BK * t * t) / BK;
        }
    }

    // last-block ticket: combine
    __threadfence();
    if (tid == 0) s_ticket = atomicAdd(&g_done, 1);
    __syncthreads();
    if (s_ticket == jme::NPAIR) {          // 129th (last) block
        float v = (tid < jme::NPAIR) ? __ldcg(&g_pair[tid]) : 0.0f;
        rA[tid] = v;
        __syncthreads();
        for (int o = 128; o > 0; o >>= 1) {
            if (tid < o) rA[tid] += rA[tid + o];
            __syncthreads();
        }
        if (tid == 0) {
            const float gg = rA[0] / (float)jme::NPAIR;
            const float ii = __ldcg(&g_ii_sum);
            out[0] = ii + gg;
            out[1] = ii;
            out[2] = gg;
            g_done = 0;                    // reset for next graph replay
        }
    }
}

// ------------------------------- launch ------------------------------------
extern "C" void kernel_launch(void* const* d_in, const int* in_sizes, int n_in,
                              void* d_out, int out_size) {
    const float* pred  = (const float*)d_in[0];
    const float* truth = (const float*)d_in[1];
    const int*   ug    = (const int*)  d_in[2];
    const int*   ig    = (const int*)  d_in[3];
    float* out = (float*)d_out;

    k_row  <<<jme::B, 256>>>(pred, truth, ig);
    k_pair <<<jme::NPAIR + 1, 256>>>(ug, out);
}